// round 1
// baseline (speedup 1.0000x reference)
#include <cuda_runtime.h>
#include <math_constants.h>
#include <cstdint>

// Shapes (fixed by the problem):
//   word_features  [B, D, T]   = [32, 256, 32]   fp32   d_in[0]
//   image_features [B, Dh,H,W] = [32, 128,128,128] fp32 d_in[1]
//   words_mask     [B, T]      = [32, 32]        int32  d_in[2]
//   W              [Dh, D]     = [128, 256]      fp32   d_in[3]
//   b              [Dh]        = [128]           fp32   d_in[4]
// Outputs (concatenated in reference return order):
//   attn               [B, Dh, N=16384]  at offset 0
//   attn_coefficients  [B, N, T]         at offset B*Dh*N

#define B_   32
#define D_   256
#define T_   32
#define DH_  128
#define N_   16384

// Scratch for values[B][Dh][T] (device global — no allocation allowed).
__device__ float g_values[B_ * DH_ * T_];

// ---------------- packed f32x2 helpers ----------------
__device__ __forceinline__ unsigned long long pk2(float lo, float hi) {
    unsigned long long r;
    asm("mov.b64 %0, {%1, %2};" : "=l"(r) : "f"(lo), "f"(hi));
    return r;
}
__device__ __forceinline__ float2 unpk2(unsigned long long v) {
    float2 f;
    asm("mov.b64 {%0, %1}, %2;" : "=f"(f.x), "=f"(f.y) : "l"(v));
    return f;
}
__device__ __forceinline__ unsigned long long ffma2(unsigned long long a,
                                                    unsigned long long b,
                                                    unsigned long long c) {
    unsigned long long d;
    asm("fma.rn.f32x2 %0, %1, %2, %3;" : "=l"(d) : "l"(a), "l"(b), "l"(c));
    return d;
}

// ---------------- kernel 1: values = W * wf + b ----------------
// grid = B, block = Dh (128). Each thread computes one k-row of values[b].
__global__ void values_kernel(const float* __restrict__ wf,
                              const float* __restrict__ Wm,
                              const float* __restrict__ bias) {
    __shared__ float swf[D_ * T_];  // 8192 floats = 32 KB, [d][t]
    const int b = blockIdx.x;
    const int k = threadIdx.x;

    const float* wfb = wf + (size_t)b * D_ * T_;
    for (int i = threadIdx.x; i < D_ * T_; i += blockDim.x)
        swf[i] = wfb[i];
    __syncthreads();

    float acc[T_];
    const float bk = bias[k];
#pragma unroll
    for (int t = 0; t < T_; t++) acc[t] = bk;

    const float* wrow = Wm + (size_t)k * D_;
#pragma unroll 4
    for (int d = 0; d < D_; d++) {
        const float w = wrow[d];
        const float4* row4 = reinterpret_cast<const float4*>(&swf[d * T_]);
#pragma unroll
        for (int j = 0; j < T_ / 4; j++) {
            float4 v = row4[j];
            acc[4 * j + 0] += w * v.x;
            acc[4 * j + 1] += w * v.y;
            acc[4 * j + 2] += w * v.z;
            acc[4 * j + 3] += w * v.w;
        }
    }

    float* outp = g_values + ((size_t)b * DH_ + k) * T_;
#pragma unroll
    for (int t = 0; t < T_; t++) outp[t] = acc[t];
}

// ---------------- kernel 2: scores + softmax + context ----------------
// grid = (N/256, B), block = 256. One thread per spatial position n.
__global__ __launch_bounds__(256)
void attn_kernel(const float* __restrict__ img,
                 const int* __restrict__ mask,
                 float* __restrict__ out_attn,
                 float* __restrict__ out_coef) {
    // values[b] as [Dh][T] fp32 = 16 KB, viewed as ulonglong2 (pairs of f32x2)
    __shared__ ulonglong2 svals[DH_ * T_ / 4];  // 1024 * 16B
    __shared__ int smask[T_];

    const int b = blockIdx.y;
    const int n = blockIdx.x * blockDim.x + threadIdx.x;

    const ulonglong2* gv =
        reinterpret_cast<const ulonglong2*>(g_values + (size_t)b * DH_ * T_);
    for (int i = threadIdx.x; i < DH_ * T_ / 4; i += 256) svals[i] = gv[i];
    if (threadIdx.x < T_) smask[threadIdx.x] = mask[b * T_ + threadIdx.x];
    __syncthreads();

    // ---- phase 1: S[t] = sum_k q[k] * vals[k][t], packed f32x2 ----
    unsigned long long S2[T_ / 2];
#pragma unroll
    for (int j = 0; j < T_ / 2; j++) S2[j] = 0ULL;

    const float* qp = img + (size_t)b * DH_ * N_ + n;
#pragma unroll 4
    for (int k = 0; k < DH_; k++) {
        const float q = qp[(size_t)k * N_];
        const unsigned long long q2 = pk2(q, q);
        const ulonglong2* vr = &svals[k * (T_ / 4)];
#pragma unroll
        for (int j = 0; j < T_ / 4; j++) {
            ulonglong2 v = vr[j];
            S2[2 * j + 0] = ffma2(q2, v.x, S2[2 * j + 0]);
            S2[2 * j + 1] = ffma2(q2, v.y, S2[2 * j + 1]);
        }
    }

    // ---- phase 2: masked softmax over T ----
    float Sv[T_];
#pragma unroll
    for (int j = 0; j < T_ / 2; j++) {
        float2 f = unpk2(S2[j]);
        Sv[2 * j + 0] = f.x;
        Sv[2 * j + 1] = f.y;
    }
    float m = -CUDART_INF_F;
#pragma unroll
    for (int t = 0; t < T_; t++) {
        if (smask[t] != 0) Sv[t] = -CUDART_INF_F;
        m = fmaxf(m, Sv[t]);
    }
    float p[T_];
    float sum = 0.f;
#pragma unroll
    for (int t = 0; t < T_; t++) {
        p[t] = __expf(Sv[t] - m);
        sum += p[t];
    }
    const float inv = 1.0f / sum;
#pragma unroll
    for (int t = 0; t < T_; t++) p[t] *= inv;

    // write attn_coefficients: [B, N, T], 32 contiguous floats per thread
    {
        float4* oc = reinterpret_cast<float4*>(
            out_coef + ((size_t)b * N_ + n) * T_);
#pragma unroll
        for (int j = 0; j < T_ / 4; j++) {
            float4 v;
            v.x = p[4 * j + 0];
            v.y = p[4 * j + 1];
            v.z = p[4 * j + 2];
            v.w = p[4 * j + 3];
            oc[j] = v;
        }
    }

    // ---- phase 3: attn[k] = sum_t vals[k][t] * p[t], packed f32x2 ----
    unsigned long long c2[T_ / 2];
#pragma unroll
    for (int j = 0; j < T_ / 2; j++) c2[j] = pk2(p[2 * j], p[2 * j + 1]);

    float* oa = out_attn + (size_t)b * DH_ * N_ + n;
#pragma unroll 2
    for (int k = 0; k < DH_; k++) {
        const ulonglong2* vr = &svals[k * (T_ / 4)];
        unsigned long long acc0 = 0ULL, acc1 = 0ULL;
#pragma unroll
        for (int j = 0; j < T_ / 4; j++) {
            ulonglong2 v = vr[j];
            acc0 = ffma2(v.x, c2[2 * j + 0], acc0);
            acc1 = ffma2(v.y, c2[2 * j + 1], acc1);
        }
        float2 f0 = unpk2(acc0);
        float2 f1 = unpk2(acc1);
        oa[(size_t)k * N_] = (f0.x + f1.x) + (f0.y + f1.y);
    }
}

extern "C" void kernel_launch(void* const* d_in, const int* in_sizes, int n_in,
                              void* d_out, int out_size) {
    const float* wf   = (const float*)d_in[0];
    const float* img  = (const float*)d_in[1];
    const int*   msk  = (const int*)d_in[2];
    const float* Wm   = (const float*)d_in[3];
    const float* bias = (const float*)d_in[4];

    float* out_attn = (float*)d_out;
    float* out_coef = (float*)d_out + (size_t)B_ * DH_ * N_;

    values_kernel<<<B_, DH_>>>(wf, Wm, bias);

    dim3 grid(N_ / 256, B_);
    attn_kernel<<<grid, 256>>>(img, msk, out_attn, out_coef);
}